// round 6
// baseline (speedup 1.0000x reference)
#include <cuda_runtime.h>

// Fixed problem shape: b=16, L=256, h=256, eh=64, M=N=128 (2M=2N=256=L).
//
// Output layout (f32 elements):
//   X1      [0,          1048576)
//   X2      [1048576,    2097152)
//   E1      [2097152,    69206016)
//   E2      [69206016,   136314880)
//   A1      [136314880,  137363456)
//   A2      [137363456,  138412032)
//   mask1   [138412032,  139460608)
//   mask2   [139460608,  140509184)
//   w1      [140509184,  140513280)
//   w2      [140513280,  140517376)
//   mask_out[140517376,  141565952)
//
// Single fused kernel. E path: 8 float4 per thread (half a 256B row) to
// maximize in-flight DRAM traffic per thread; index math amortized 8x.

#define AMW_BLOCKS 5128u
#define X_BLOCKS   2048u
#define E_BLOCKS   16384u   // 2*16*256*256 rows * 2 threads/row / 256 = 16384 blocks

__global__ void __launch_bounds__(256) fused_kernel(
    const float4* __restrict__ E4,
    const float4* __restrict__ X4,
    const float*  __restrict__ A,
    const float4* __restrict__ mask4,
    const int*    __restrict__ mol,
    float*        __restrict__ out)
{
    unsigned bid = blockIdx.x;
    float4* out4 = reinterpret_cast<float4*>(out);

    if (bid >= AMW_BLOCKS + X_BLOCKS) {
        // ------------------------------------------------------------------
        // E1 / E2 gather: 8 float4 per thread. g in [0, 4194304).
        // row r = g>>1 (bits [20]=t [19:16]=bi [15:8]=i [7:0]=j), kb = g&1.
        // thread covers f4 offsets kb, kb+2, ..., kb+14 of the row.
        // ------------------------------------------------------------------
        unsigned g = (bid - (AMW_BLOCKS + X_BLOCKS)) * 256u + threadIdx.x;
        unsigned r = g >> 1;
        int kb = g & 1;
        int t  = r >> 20;
        int bi = (r >> 16) & 15;
        int i  = (r >> 8)  & 255;
        int j  = r & 255;

        int l0 = __ldg(&mol[bi * 2]);
        int l  = t ? __ldg(&mol[bi * 2 + 1]) : l0;

        bool fi = i < l;
        bool fj = j < l;
        bool si = !fi && (i < 2 * l);
        bool sj = !fj && (j < 2 * l);
        bool valid = (fi && fj) || (si && sj);

        unsigned obase = t ? 17301504u : 524288u;
        unsigned d = obase + ((r & 0xFFFFFu) << 4) + (unsigned)kb;

        if (valid) {
            int ri = fi ? i : i - l;
            int rj = fj ? j : j - l;
            if (t) {
                ri = min(ri + l0, 255);
                rj = min(rj + l0, 255);
            }
            unsigned s = (unsigned)((((bi << 8) + ri) << 8) + rj) * 16u + (unsigned)kb;
            float4 v0 = __ldg(&E4[s]);
            float4 v1 = __ldg(&E4[s + 2]);
            float4 v2 = __ldg(&E4[s + 4]);
            float4 v3 = __ldg(&E4[s + 6]);
            float4 v4 = __ldg(&E4[s + 8]);
            float4 v5 = __ldg(&E4[s + 10]);
            float4 v6 = __ldg(&E4[s + 12]);
            float4 v7 = __ldg(&E4[s + 14]);
            out4[d]      = v0;
            out4[d + 2]  = v1;
            out4[d + 4]  = v2;
            out4[d + 6]  = v3;
            out4[d + 8]  = v4;
            out4[d + 10] = v5;
            out4[d + 12] = v6;
            out4[d + 14] = v7;
        } else {
            float4 z = make_float4(0.f, 0.f, 0.f, 0.f);
            out4[d]      = z;
            out4[d + 2]  = z;
            out4[d + 4]  = z;
            out4[d + 6]  = z;
            out4[d + 8]  = z;
            out4[d + 10] = z;
            out4[d + 12] = z;
            out4[d + 14] = z;
        }
        return;
    }

    if (bid >= AMW_BLOCKS) {
        // ------------------------------------------------------------------
        // X1 / X2: idx bits [18]=t [17:14]=bi [13:6]=p [5:0]=k4
        // ------------------------------------------------------------------
        unsigned idx = (bid - AMW_BLOCKS) * 256u + threadIdx.x;
        int t  = idx >> 18;
        int bi = (idx >> 14) & 15;
        int p  = (idx >> 6)  & 255;
        int k4 = idx & 63;

        int l = __ldg(&mol[bi * 2 + t]);

        float4 v = make_float4(0.f, 0.f, 0.f, 0.f);
        if (p < 2 * l) {
            int sp = (p < l) ? p : p - l;
            v = __ldg(&X4[(unsigned)(((bi << 8) + sp) << 6) + (unsigned)k4]);
        }
        out4[(t ? 262144u : 0u) + (idx & 0x0003FFFFu)] = v;
        return;
    }

    // ----------------------------------------------------------------------
    // amw: A1/A2/mask1/mask2 [0,1048576), mask_out [1048576,1310720),
    //      w zeros [1310720,1312768)
    // ----------------------------------------------------------------------
    unsigned idx = bid * 256u + threadIdx.x;

    if (idx < 1048576u) {
        int t2 = idx >> 18;          // 0:A1 1:A2 2:mask1 3:mask2
        int bi = (idx >> 14) & 15;
        int i  = (idx >> 6)  & 255;
        int j0 = (idx & 63) * 4;
        int tt = t2 & 1;

        int l0 = __ldg(&mol[bi * 2]);
        int l  = tt ? __ldg(&mol[bi * 2 + 1]) : l0;

        bool fi = i < l;
        bool si = !fi && (i < 2 * l);
        int ri = fi ? i : i - l;
        if (tt) ri = min(ri + l0, 255);

        float4 v;
        float* vv = &v.x;
        #pragma unroll
        for (int q = 0; q < 4; q++) {
            int j = j0 + q;
            bool fj = j < l;
            bool sj = !fj && (j < 2 * l);
            if (t2 < 2) {
                float a = 0.f;
                if ((fi && fj) || (si && sj)) {
                    int rj = fj ? j : j - l;
                    if (tt) rj = min(rj + l0, 255);
                    a = __ldg(&A[(unsigned)(bi << 16) + (unsigned)(ri << 8) + (unsigned)rj]);
                }
                vv[q] = a;
            } else {
                bool bad = (fi && sj) || (si && fj);
                vv[q] = bad ? 0.f : 1.f;
            }
        }
        out4[34078720u + (unsigned)t2 * 262144u + (idx & 0x0003FFFFu)] = v;
    }
    else if (idx < 1310720u) {
        unsigned m = idx - 1048576u;
        int bi = (m >> 14) & 15;
        int i  = (m >> 6)  & 255;
        int j0 = (m & 63) * 4;

        int l0 = __ldg(&mol[bi * 2]);
        int l1 = __ldg(&mol[bi * 2 + 1]);
        int lsum = l0 + l1;

        bool li = i < l0;
        bool mi = !li && (i < lsum);

        float4 mb = __ldg(&mask4[((unsigned)(bi << 16) + (unsigned)(i << 8) + (unsigned)j0) >> 2]);
        const float* mbp = &mb.x;

        float4 v;
        float* vv = &v.x;
        #pragma unroll
        for (int q = 0; q < 4; q++) {
            int j = j0 + q;
            bool lj = j < l0;
            bool mj = !lj && (j < lsum);
            float r;
            if (li == lj)                        r = 1.f;
            else if ((li && mj) || (mi && lj))   r = 0.f;
            else r = (mbp[q] != 0.f) ? 1.f : 0.f;
            vv[q] = r;
        }
        out4[35129344u + m] = v;
    }
    else if (idx < 1312768u) {
        out4[35127296u + (idx - 1310720u)] = make_float4(0.f, 0.f, 0.f, 0.f);
    }
}

extern "C" void kernel_launch(void* const* d_in, const int* in_sizes, int n_in,
                              void* d_out, int out_size)
{
    const float4* X    = (const float4*)d_in[0];
    const float4* E    = (const float4*)d_in[1];
    const float*  A    = (const float*)d_in[2];
    // d_in[3] = w (unused: w1/w2 are zeros)
    const float4* mask = (const float4*)d_in[4];
    const int*    mol  = (const int*)d_in[5];
    float*        out  = (float*)d_out;

    fused_kernel<<<AMW_BLOCKS + X_BLOCKS + E_BLOCKS, 256>>>(E, X, A, mask, mol, out);
}

// round 7
// speedup vs baseline: 1.0809x; 1.0809x over previous
#include <cuda_runtime.h>

// Fixed problem shape: b=16, L=256, h=256, eh=64, M=N=128 (2M=2N=256=L).
//
// Output layout (f32 elements):
//   X1      [0,          1048576)
//   X2      [1048576,    2097152)
//   E1      [2097152,    69206016)
//   E2      [69206016,   136314880)
//   A1      [136314880,  137363456)
//   A2      [137363456,  138412032)
//   mask1   [138412032,  139460608)
//   mask2   [139460608,  140509184)
//   w1      [140509184,  140513280)
//   w2      [140513280,  140517376)
//   mask_out[140517376,  141565952)
//
// Single fused kernel. Block roles are INTERLEAVED so the small amw/X blocks
// are spread evenly among the DRAM-saturating E blocks (no low-BW leading
// waves). E path = R4 layout: 4 threads/row, each thread 4 float4 at +4
// stride (per-instruction warp footprint = 8 rows x contiguous 64B).

#define SMALL_BLOCKS 7176u    // 5128 amw + 2048 X
#define E_BLOCKS     32768u
#define TOTAL_BLOCKS 39944u

__global__ void __launch_bounds__(256) fused_kernel(
    const float4* __restrict__ E4,
    const float4* __restrict__ X4,
    const float*  __restrict__ A,
    const float4* __restrict__ mask4,
    const int*    __restrict__ mol,
    float*        __restrict__ out)
{
    unsigned bid = blockIdx.x;
    float4* out4 = reinterpret_cast<float4*>(out);

    // Evenly interleave SMALL_BLOCKS among TOTAL_BLOCKS:
    // block b is "small" iff floor((b+1)*S/T) > floor(b*S/T).
    unsigned long long num = (unsigned long long)bid * SMALL_BLOCKS;
    unsigned f0 = (unsigned)(num / TOTAL_BLOCKS);
    unsigned f1 = (unsigned)((num + SMALL_BLOCKS) / TOTAL_BLOCKS);
    bool is_small = (f1 > f0);

    if (!is_small) {
        // ------------------------------------------------------------------
        // E1 / E2 gather: 4 float4 per thread (kb, kb+4, kb+8, kb+12).
        // g in [0, 8388608). row r = g>>2 (bits [20]=t [19:16]=bi [15:8]=i
        // [7:0]=j), kb = g&3.
        // ------------------------------------------------------------------
        unsigned eb = bid - f0;                 // E block index in [0, 32768)
        unsigned g = eb * 256u + threadIdx.x;
        unsigned r = g >> 2;
        int kb = g & 3;
        int t  = r >> 20;
        int bi = (r >> 16) & 15;
        int i  = (r >> 8)  & 255;
        int j  = r & 255;

        int l0 = __ldg(&mol[bi * 2]);
        int l  = t ? __ldg(&mol[bi * 2 + 1]) : l0;

        bool fi = i < l;
        bool fj = j < l;
        bool si = !fi && (i < 2 * l);
        bool sj = !fj && (j < 2 * l);
        bool valid = (fi && fj) || (si && sj);

        unsigned obase = t ? 17301504u : 524288u;
        unsigned d = obase + ((r & 0xFFFFFu) << 4) + (unsigned)kb;

        if (valid) {
            int ri = fi ? i : i - l;
            int rj = fj ? j : j - l;
            if (t) {
                ri = min(ri + l0, 255);
                rj = min(rj + l0, 255);
            }
            unsigned s = (unsigned)((((bi << 8) + ri) << 8) + rj) * 16u + (unsigned)kb;
            float4 v0 = __ldg(&E4[s]);
            float4 v1 = __ldg(&E4[s + 4]);
            float4 v2 = __ldg(&E4[s + 8]);
            float4 v3 = __ldg(&E4[s + 12]);
            out4[d]      = v0;
            out4[d + 4]  = v1;
            out4[d + 8]  = v2;
            out4[d + 12] = v3;
        } else {
            float4 z = make_float4(0.f, 0.f, 0.f, 0.f);
            out4[d]      = z;
            out4[d + 4]  = z;
            out4[d + 8]  = z;
            out4[d + 12] = z;
        }
        return;
    }

    unsigned sb = f0;                           // small block index in [0, 7176)

    if (sb >= 5128u) {
        // ------------------------------------------------------------------
        // X1 / X2: idx bits [18]=t [17:14]=bi [13:6]=p [5:0]=k4
        // ------------------------------------------------------------------
        unsigned idx = (sb - 5128u) * 256u + threadIdx.x;
        int t  = idx >> 18;
        int bi = (idx >> 14) & 15;
        int p  = (idx >> 6)  & 255;
        int k4 = idx & 63;

        int l = __ldg(&mol[bi * 2 + t]);

        float4 v = make_float4(0.f, 0.f, 0.f, 0.f);
        if (p < 2 * l) {
            int sp = (p < l) ? p : p - l;
            v = __ldg(&X4[(unsigned)(((bi << 8) + sp) << 6) + (unsigned)k4]);
        }
        out4[(t ? 262144u : 0u) + (idx & 0x0003FFFFu)] = v;
        return;
    }

    // ----------------------------------------------------------------------
    // amw: A1/A2/mask1/mask2 [0,1048576), mask_out [1048576,1310720),
    //      w zeros [1310720,1312768)
    // ----------------------------------------------------------------------
    unsigned idx = sb * 256u + threadIdx.x;

    if (idx < 1048576u) {
        int t2 = idx >> 18;          // 0:A1 1:A2 2:mask1 3:mask2
        int bi = (idx >> 14) & 15;
        int i  = (idx >> 6)  & 255;
        int j0 = (idx & 63) * 4;
        int tt = t2 & 1;

        int l0 = __ldg(&mol[bi * 2]);
        int l  = tt ? __ldg(&mol[bi * 2 + 1]) : l0;

        bool fi = i < l;
        bool si = !fi && (i < 2 * l);
        int ri = fi ? i : i - l;
        if (tt) ri = min(ri + l0, 255);

        float4 v;
        float* vv = &v.x;
        #pragma unroll
        for (int q = 0; q < 4; q++) {
            int j = j0 + q;
            bool fj = j < l;
            bool sj = !fj && (j < 2 * l);
            if (t2 < 2) {
                float a = 0.f;
                if ((fi && fj) || (si && sj)) {
                    int rj = fj ? j : j - l;
                    if (tt) rj = min(rj + l0, 255);
                    a = __ldg(&A[(unsigned)(bi << 16) + (unsigned)(ri << 8) + (unsigned)rj]);
                }
                vv[q] = a;
            } else {
                bool bad = (fi && sj) || (si && fj);
                vv[q] = bad ? 0.f : 1.f;
            }
        }
        out4[34078720u + (unsigned)t2 * 262144u + (idx & 0x0003FFFFu)] = v;
    }
    else if (idx < 1310720u) {
        unsigned m = idx - 1048576u;
        int bi = (m >> 14) & 15;
        int i  = (m >> 6)  & 255;
        int j0 = (m & 63) * 4;

        int l0 = __ldg(&mol[bi * 2]);
        int l1 = __ldg(&mol[bi * 2 + 1]);
        int lsum = l0 + l1;

        bool li = i < l0;
        bool mi = !li && (i < lsum);

        float4 mb = __ldg(&mask4[((unsigned)(bi << 16) + (unsigned)(i << 8) + (unsigned)j0) >> 2]);
        const float* mbp = &mb.x;

        float4 v;
        float* vv = &v.x;
        #pragma unroll
        for (int q = 0; q < 4; q++) {
            int j = j0 + q;
            bool lj = j < l0;
            bool mj = !lj && (j < lsum);
            float r;
            if (li == lj)                        r = 1.f;
            else if ((li && mj) || (mi && lj))   r = 0.f;
            else r = (mbp[q] != 0.f) ? 1.f : 0.f;
            vv[q] = r;
        }
        out4[35129344u + m] = v;
    }
    else if (idx < 1312768u) {
        out4[35127296u + (idx - 1310720u)] = make_float4(0.f, 0.f, 0.f, 0.f);
    }
}

extern "C" void kernel_launch(void* const* d_in, const int* in_sizes, int n_in,
                              void* d_out, int out_size)
{
    const float4* X    = (const float4*)d_in[0];
    const float4* E    = (const float4*)d_in[1];
    const float*  A    = (const float*)d_in[2];
    // d_in[3] = w (unused: w1/w2 are zeros)
    const float4* mask = (const float4*)d_in[4];
    const int*    mol  = (const int*)d_in[5];
    float*        out  = (float*)d_out;

    fused_kernel<<<TOTAL_BLOCKS, 256>>>(E, X, A, mask, mol, out);
}